// round 16
// baseline (speedup 1.0000x reference)
#include <cuda_runtime.h>
#include <cuda_fp16.h>
#include <math.h>

#define BB 128
#define NN 4096
#define DD 64
#define SS 7
#define HH 128
#define NUM_ITERS 3
#define EPSV 1e-8f
#define LN_EPS 1e-5f
#define SCALE 0.125f   // 64^-0.5

typedef unsigned long long u64;
typedef unsigned int u32;

#define PDL_TRIGGER() asm volatile("griddepcontrol.launch_dependents;")
#define PDL_WAIT()    asm volatile("griddepcontrol.wait;" ::: "memory")

// persistent scratch (no allocation allowed)
__device__ float g_slots[BB*SS*DD];
__device__ float g_qt[BB*SS*DD];    // qw = ln_in_w ⊙ (q@Wk)  [b][s][64]
__device__ float g_qsc[BB*SS*2];    // {sw, sb} per (b,s)
__device__ float g_u[BB*SS*DD];     // G1 = sum_n (p*r) * x
__device__ float g_den[BB*SS];      // sum_n p
__device__ float g_c2[BB*SS];       // sum_n p*r*m
__device__ float g_M[DD*DD];        // scale * Wq^T @ Wk      [e][t]
__device__ float g_CT[DD*3*DD];     // (W_ih @ Wv)^T          [e][j]
__device__ float g_WHHT[DD*3*DD];   // W_hh^T                 [e][j]
__device__ float g_W1T[DD*HH];      // W1^T                   [e][j]
__device__ float g_W2T[HH*DD];      // W2^T                   [j][d]
__device__ __half g_xh[(size_t)BB*NN*DD];   // fp16 shadow of inputs (67MB)
__device__ float g_sq[(size_t)BB*NN];       // per-token sumsq cache (2MB)

// ---------------------------------------------------------------------------
__device__ __forceinline__ float fexp(float x){
    float t = fmaxf(x * 1.4426950408889634f, -126.f);
    float z = __fadd_rn(t, 12582912.f);
    int n = __float_as_int(z) - 0x4B400000;
    float f = t - __fsub_rn(z, 12582912.f);
    float p =         1.5403530e-4f;
    p = fmaf(p, f,    1.3333558e-3f);
    p = fmaf(p, f,    9.6181291e-3f);
    p = fmaf(p, f,    5.5504109e-2f);
    p = fmaf(p, f,    2.4022651e-1f);
    p = fmaf(p, f,    6.9314718e-1f);
    p = fmaf(p, f,    1.0f);
    return p * __int_as_float((n + 127) << 23);
}
__device__ __forceinline__ float ftanh(float x){
    return 1.f - __fdividef(2.f, 1.f + __expf(2.f*x));
}
__device__ __forceinline__ u32 smaddr(const void* p){
    return (u32)__cvta_generic_to_shared(p);
}
__device__ __forceinline__ void ldm_x4(u32& r0, u32& r1, u32& r2, u32& r3, u32 a){
    asm volatile("ldmatrix.sync.aligned.m8n8.x4.shared.b16 {%0,%1,%2,%3}, [%4];"
                 : "=r"(r0), "=r"(r1), "=r"(r2), "=r"(r3) : "r"(a));
}
__device__ __forceinline__ void ldm_x2t(u32& r0, u32& r1, u32 a){
    asm volatile("ldmatrix.sync.aligned.m8n8.x2.trans.shared.b16 {%0,%1}, [%2];"
                 : "=r"(r0), "=r"(r1) : "r"(a));
}
__device__ __forceinline__ void mma16816(float& d0, float& d1, float& d2, float& d3,
                                         u32 a0, u32 a1, u32 a2, u32 a3,
                                         u32 b0, u32 b1){
    asm volatile("mma.sync.aligned.m16n8k16.row.col.f32.f16.f16.f32 "
                 "{%0,%1,%2,%3}, {%4,%5,%6,%7}, {%8,%9}, {%0,%1,%2,%3};"
                 : "+f"(d0), "+f"(d1), "+f"(d2), "+f"(d3)
                 : "r"(a0), "r"(a1), "r"(a2), "r"(a3), "r"(b0), "r"(b1));
}

// ---------------------------------------------------------------------------
__global__ void k_precomp(const float* __restrict__ Wq,
                          const float* __restrict__ Wk,
                          const float* __restrict__ W_ih,
                          const float* __restrict__ Wv,
                          const float* __restrict__ W_hh,
                          const float* __restrict__ W1,
                          const float* __restrict__ W2) {
    int bi = blockIdx.x, t = threadIdx.x;
    if (bi < 16) {
        int o = bi*256 + t;
        int e = o >> 6, tc = o & 63;
        float acc = 0.f;
        #pragma unroll 8
        for (int d = 0; d < 64; d++)
            acc += Wq[d*64 + e] * Wk[d*64 + tc];
        g_M[e*64 + tc] = acc * SCALE;
    } else if (bi < 64) {
        int o = (bi-16)*256 + t;
        int e = o / 192, j = o - e*192;
        float acc = 0.f;
        #pragma unroll 8
        for (int h = 0; h < 64; h++)
            acc += W_ih[j*64 + h] * Wv[h*64 + e];
        g_CT[o] = acc;
    } else {
        int idx = (bi-64)*256 + t;
        if (idx < 12288) {
            int e = idx / 192, j = idx - e*192;
            g_WHHT[idx] = W_hh[j*64 + e];
        } else if (idx < 20480) {
            int o = idx - 12288;
            int e = o >> 7, j = o & 127;
            g_W1T[o] = W1[j*64 + e];
        } else {
            int o = idx - 20480;
            int j = o >> 6, d = o & 63;
            g_W2T[o] = W2[d*128 + j];
        }
    }
}

// ---------------------------------------------------------------------------
__global__ void k_q0(const float* __restrict__ noise,
                     const float* __restrict__ mu,
                     const float* __restrict__ logsig,
                     const float* __restrict__ lnw,
                     const float* __restrict__ lnb,
                     const float* __restrict__ w_in,
                     const float* __restrict__ b_in) {
    int b = blockIdx.x;
    int tid = threadIdx.x;
    int w = tid >> 5, lane = tid & 31;
    __shared__ float sl[SS*64];
    __shared__ float sn[SS*64];
    __shared__ float qtmp[SS*64];

    PDL_TRIGGER();

    for (int i = tid; i < SS*64; i += 256) {
        int d = i & 63;
        float v = mu[d] + expf(logsig[d]) * noise[b*SS*64 + i];
        g_slots[b*SS*64 + i] = v;
        sl[i] = v;
        g_u[b*SS*64 + i] = 0.f;
    }
    if (tid < SS) { g_den[b*SS + tid] = 0.f; g_c2[b*SS + tid] = 0.f; }
    __syncthreads();

    if (w < SS) {
        float v0 = sl[w*64 + lane], v1 = sl[w*64 + lane+32];
        float sum = v0 + v1, sq = v0*v0 + v1*v1;
        #pragma unroll
        for (int o = 16; o; o >>= 1) {
            sum += __shfl_xor_sync(0xffffffffu, sum, o);
            sq  += __shfl_xor_sync(0xffffffffu, sq,  o);
        }
        float mean = sum * (1.f/64.f);
        float var  = sq  * (1.f/64.f) - mean*mean;
        float rstd = rsqrtf(var + LN_EPS);
        sn[w*64 + lane]    = (v0 - mean)*rstd*lnw[lane]    + lnb[lane];
        sn[w*64 + lane+32] = (v1 - mean)*rstd*lnw[lane+32] + lnb[lane+32];
    }
    PDL_WAIT();
    __syncthreads();

    for (int i = tid; i < SS*64; i += 256) {
        int s = i >> 6, tc = i & 63;
        float acc = 0.f;
        #pragma unroll 8
        for (int e = 0; e < 64; e++)
            acc += sn[s*64 + e] * g_M[e*64 + tc];
        qtmp[i] = acc;
        g_qt[b*SS*64 + i] = acc * w_in[tc];
    }
    __syncthreads();
    if (tid < 14) {
        int s = tid >> 1;
        float acc = 0.f;
        if ((tid & 1) == 0) {
            for (int tc = 0; tc < 64; tc++) acc += qtmp[s*64+tc] * w_in[tc];
        } else {
            for (int tc = 0; tc < 64; tc++) acc += qtmp[s*64+tc] * b_in[tc];
        }
        g_qsc[b*SS*2 + tid] = acc;
    }
}

// ---------------------------------------------------------------------------
// Tensor-core streaming pass, 512-token tiles (1024 blocks).
// smem bytes:
//   XH  fp16 [512][72]  : 0      .. 73728
//   PRS fp16 [16][520]  : 73728  .. 90368   (rows 0..6 valid)
//   QH  fp16 [8][68]    : 90368  .. 91456   (row 7 = ones -> sum column)
//   SQV f32  [512]      : 91456  .. 93504
//   QSC f32  [14]       : 93504  .. 93560
#define O_XH   0
#define O_PRS  73728
#define O_QH   90368
#define O_SQV  91456
#define O_QSC  93504
#define AT_BYTES 93568
#define TT 512   // tokens per tile

template<int FIRST>
__global__ void __launch_bounds__(256) k_attn(const float* __restrict__ inputs) {
    extern __shared__ char sm[];
    __half* xh  = (__half*)(sm + O_XH);
    __half* prs = (__half*)(sm + O_PRS);
    __half* qh  = (__half*)(sm + O_QH);
    float*  sqv = (float*)(sm + O_SQV);
    float*  qsc = (float*)(sm + O_QSC);

    int b = blockIdx.y, tile = blockIdx.x;
    int tid = threadIdx.x;
    int w = tid >> 5, lane = tid & 31;
    int g = lane >> 2, q = lane & 3;

    PDL_TRIGGER();

    size_t base = ((size_t)b*NN + (size_t)tile*TT) * DD;
    size_t sqbase = (size_t)b*NN + (size_t)tile*TT;
    if (FIRST) {
        const float4* src4 = (const float4*)(inputs + base);
        __half2* dsth = (__half2*)(g_xh + base);
        #pragma unroll
        for (int k = 0; k < 32; k++) {
            int idx = tid + 256*k;
            float4 v = src4[idx];
            int token = idx >> 4, ch = idx & 15;
            __half2 h0 = __floats2half2_rn(v.x, v.y);
            __half2 h1 = __floats2half2_rn(v.z, v.w);
            uint2 pk2;
            pk2.x = *(u32*)&h0; pk2.y = *(u32*)&h1;
            *(uint2*)(xh + token*72 + ch*4) = pk2;
            *(uint2*)(dsth + idx*2) = pk2;
        }
        __syncthreads();
        // per-token sumsq from fp16 smem (2 tokens per thread); cache to g_sq
        #pragma unroll
        for (int tt = 0; tt < 2; tt++) {
            int t = tid + 256*tt;
            const uint4* p = (const uint4*)(xh + t*72);
            float sq = 0.f;
            #pragma unroll
            for (int j = 0; j < 8; j++) {
                uint4 v = p[j];
                float2 f;
                f = __half22float2(*(__half2*)&v.x); sq = fmaf(f.x,f.x,fmaf(f.y,f.y,sq));
                f = __half22float2(*(__half2*)&v.y); sq = fmaf(f.x,f.x,fmaf(f.y,f.y,sq));
                f = __half22float2(*(__half2*)&v.z); sq = fmaf(f.x,f.x,fmaf(f.y,f.y,sq));
                f = __half22float2(*(__half2*)&v.w); sq = fmaf(f.x,f.x,fmaf(f.y,f.y,sq));
            }
            sqv[t] = sq;
            g_sq[sqbase + t] = sq;
        }
    } else {
        const uint4* srch = (const uint4*)(g_xh + base);
        #pragma unroll
        for (int it = 0; it < 16; it++) {
            int idx = tid + 256*it;
            uint4 v = srch[idx];
            int token = idx >> 3, c8 = idx & 7;
            *(uint4*)(xh + token*72 + c8*8) = v;
        }
        sqv[tid]       = g_sq[sqbase + tid];
        sqv[tid + 256] = g_sq[sqbase + tid + 256];
    }

    PDL_WAIT();      // g_qt/g_qsc from predecessor

    for (int i = tid; i < 8*64; i += 256) {
        int s = i >> 6, k = i & 63;
        qh[s*68 + k] = (s < SS) ? __float2half(g_qt[b*SS*64 + s*64 + k])
                                : __float2half(1.0f);    // ones row -> sum
    }
    if (tid < 14) qsc[tid] = g_qsc[b*14 + tid];
    __syncthreads();

    // ---- phase A: four 16-token MMA groups per warp + softmax ----
    float dvA0 = 0.f, cvA0 = 0.f, dvA1 = 0.f, cvA1 = 0.f;
    u32 xh_s = smaddr(xh);
    int s0 = q*2, s1 = q*2 + 1;
    bool v1 = (s1 < SS);
    #pragma unroll
    for (int tg = 0; tg < 4; tg++) {
        int t0 = w*64 + tg*16;
        float d0 = 0.f, d1 = 0.f, d2 = 0.f, d3 = 0.f;
        #pragma unroll
        for (int kt = 0; kt < 4; kt++) {
            u32 a0, a1, a2, a3;
            u32 addr = xh_s + ((t0 + (lane & 15))*72 + kt*16 + (lane >> 4)*8)*2;
            ldm_x4(a0, a1, a2, a3, addr);
            u32 b01 = *(const u32*)(qh + g*68 + kt*16 + q*2);
            u32 b23 = *(const u32*)(qh + g*68 + kt*16 + 8 + q*2);
            mma16816(d0, d1, d2, d3, a0, a1, a2, a3, b01, b23);
        }
        int r0 = t0 + g, r1 = t0 + g + 8;
        float sum0 = __shfl_sync(0xffffffffu, d1, g*4 + 3);
        float sum1 = __shfl_sync(0xffffffffu, d3, g*4 + 3);
        float m0 = sum0 * (1.f/64.f), m1 = sum1 * (1.f/64.f);
        float rs0 = rsqrtf(fmaf(sqv[r0], 1.f/64.f, -m0*m0) + LN_EPS);
        float rs1 = rsqrtf(fmaf(sqv[r1], 1.f/64.f, -m1*m1) + LN_EPS);

        float lg00 = fmaf(rs0, d0 - m0*qsc[2*s0], qsc[2*s0+1]);
        float lg10 = fmaf(rs1, d2 - m1*qsc[2*s0], qsc[2*s0+1]);
        float lg01 = v1 ? fmaf(rs0, d1 - m0*qsc[2*s1], qsc[2*s1+1]) : -1e30f;
        float lg11 = v1 ? fmaf(rs1, d3 - m1*qsc[2*s1], qsc[2*s1+1]) : -1e30f;

        float mx0 = fmaxf(lg00, lg01), mx1 = fmaxf(lg10, lg11);
        #pragma unroll
        for (int o = 1; o <= 2; o <<= 1) {
            mx0 = fmaxf(mx0, __shfl_xor_sync(0xffffffffu, mx0, o));
            mx1 = fmaxf(mx1, __shfl_xor_sync(0xffffffffu, mx1, o));
        }
        float e00 = fexp(lg00 - mx0), e01 = v1 ? fexp(lg01 - mx0) : 0.f;
        float e10 = fexp(lg10 - mx1), e11 = v1 ? fexp(lg11 - mx1) : 0.f;
        float tot0 = e00 + e01, tot1 = e10 + e11;
        #pragma unroll
        for (int o = 1; o <= 2; o <<= 1) {
            tot0 += __shfl_xor_sync(0xffffffffu, tot0, o);
            tot1 += __shfl_xor_sync(0xffffffffu, tot1, o);
        }
        float inv0 = __fdividef(1.f, tot0), inv1 = __fdividef(1.f, tot1);

        float p00 = fmaf(e00, inv0, EPSV), p10 = fmaf(e10, inv1, EPSV);
        float p01 = fmaf(e01, inv0, EPSV), p11 = fmaf(e11, inv1, EPSV);
        float pr00 = p00*rs0, pr10 = p10*rs1;
        float pr01 = p01*rs0, pr11 = p11*rs1;

        prs[s0*520 + r0] = __float2half(pr00);
        prs[s0*520 + r1] = __float2half(pr10);
        if (v1) {
            prs[s1*520 + r0] = __float2half(pr01);
            prs[s1*520 + r1] = __float2half(pr11);
        }
        dvA0 += p00 + p10;  cvA0 += pr00*m0 + pr10*m1;
        if (v1) { dvA1 += p01 + p11;  cvA1 += pr01*m0 + pr11*m1; }
    }
    #pragma unroll
    for (int o = 4; o <= 16; o <<= 1) {
        dvA0 += __shfl_xor_sync(0xffffffffu, dvA0, o);
        cvA0 += __shfl_xor_sync(0xffffffffu, cvA0, o);
        dvA1 += __shfl_xor_sync(0xffffffffu, dvA1, o);
        cvA1 += __shfl_xor_sync(0xffffffffu, cvA1, o);
    }
    if (lane < 4) {
        int ss0 = lane*2, ss1 = lane*2 + 1;
        atomicAdd(&g_den[b*SS + ss0], dvA0);
        atomicAdd(&g_c2[b*SS + ss0],  cvA0);
        if (ss1 < SS) {
            atomicAdd(&g_den[b*SS + ss1], dvA1);
            atomicAdd(&g_c2[b*SS + ss1],  cvA1);
        }
    }
    __syncthreads();

    // ---- phase B: U = PR^T @ X via HMMA. warp w -> e-cols n0..n0+7 ----
    {
        int n0 = w*8;
        float u0 = 0.f, u1 = 0.f, u2 = 0.f, u3 = 0.f;
        u32 prs_s = smaddr(prs);
        #pragma unroll
        for (int kt = 0; kt < 32; kt++) {
            u32 a0, a1, a2, a3, b0, b1;
            u32 addrA = prs_s + ((lane & 15)*520 + kt*16 + (lane >> 4)*8)*2;
            ldm_x4(a0, a1, a2, a3, addrA);
            u32 addrB = xh_s + ((kt*16 + (lane & 15))*72 + n0)*2;
            ldm_x2t(b0, b1, addrB);
            mma16816(u0, u1, u2, u3, a0, a1, a2, a3, b0, b1);
        }
        if (g < SS) {
            float* up = g_u + (b*SS + g)*DD + n0 + q*2;
            atomicAdd(up + 0, u0);
            atomicAdd(up + 1, u1);
        }
        (void)u2; (void)u3;
    }
}

// ---------------------------------------------------------------------------
// finalize: one block per (batch, slot) = 896 blocks, 192 threads.
__global__ void __launch_bounds__(192, 4) k_finalize(
        const float* __restrict__ b_ih, const float* __restrict__ b_hh,
        const float* __restrict__ b1,  const float* __restrict__ b2,
        const float* __restrict__ ln_mlp_w, const float* __restrict__ ln_mlp_b,
        const float* __restrict__ ln_slots_w, const float* __restrict__ ln_slots_b,
        const float* __restrict__ ln_in_w, const float* __restrict__ ln_in_b,
        float* __restrict__ out, int last, int early) {
    __shared__ float upd[64], prev[64], giv[192], ghv[192],
                     act[64], mln[64], h1[128], red[8];
    int bs = blockIdx.x;
    int tid = threadIdx.x;

    if (early) PDL_TRIGGER();

    {   // prefetch weights while predecessor attn drains
        float acc = 0.f;
        #pragma unroll 8
        for (int e = 0; e < 64; e++)
            acc += g_CT[e*192 + tid] + g_WHHT[e*192 + tid];
        if (tid < 128) {
            #pragma unroll 8
            for (int e = 0; e < 64; e++) acc += g_W1T[e*128 + tid];
        }
        if (tid < 64) {
            #pragma unroll 8
            for (int j = 0; j < 128; j++) acc += g_W2T[j*64 + tid];
            #pragma unroll 8
            for (int e = 0; e < 64; e++) acc += g_M[e*64 + tid];
        }
        asm volatile("" :: "f"(acc));
    }

    PDL_WAIT();

    if (tid < 64) {
        float invden = __fdividef(1.f, g_den[bs]);
        upd[tid] = fmaf(ln_in_w[tid]*invden, g_u[bs*64 + tid] - g_c2[bs],
                        ln_in_b[tid]);
        prev[tid] = g_slots[bs*64 + tid];
    }
    __syncthreads();

    {
        float ai0 = b_ih[tid], ah0 = b_hh[tid];
        float ai1 = 0.f, ah1 = 0.f, ai2 = 0.f, ah2 = 0.f, ai3 = 0.f, ah3 = 0.f;
        #pragma unroll 8
        for (int e = 0; e < 64; e += 4) {
            ai0 = fmaf(upd[e],    g_CT[e*192 + tid],       ai0);
            ai1 = fmaf(upd[e+1],  g_CT[(e+1)*192 + tid],   ai1);
            ai2 = fmaf(upd[e+2],  g_CT[(e+2)*192 + tid],   ai2);
            ai3 = fmaf(upd[e+3],  g_CT[(e+3)*192 + tid],   ai3);
            ah0 = fmaf(prev[e],   g_WHHT[e*192 + tid],     ah0);
            ah1 = fmaf(prev[e+1], g_WHHT[(e+1)*192 + tid], ah1);
            ah2 = fmaf(prev[e+2], g_WHHT[(e+2)*192 + tid], ah2);
            ah3 = fmaf(prev[e+3], g_WHHT[(e+3)*192 + tid], ah3);
        }
        giv[tid] = (ai0 + ai1) + (ai2 + ai3);
        ghv[tid] = (ah0 + ah1) + (ah2 + ah3);
    }
    __syncthreads();

    if (tid < 64) {
        float r = 1.f/(1.f + __expf(-(giv[tid]     + ghv[tid])));
        float z = 1.f/(1.f + __expf(-(giv[64+tid]  + ghv[64+tid])));
        float n = ftanh(fmaf(r, ghv[128+tid], giv[128+tid]));
        float v = (1.f - z)*n + z*prev[tid];
        act[tid] = v;
        float sum = v, sq = v*v;
        #pragma unroll
        for (int o = 16; o; o >>= 1) {
            sum += __shfl_xor_sync(0xffffffffu, sum, o);
            sq  += __shfl_xor_sync(0xffffffffu, sq,  o);
        }
        if ((tid & 31) == 0) { red[(tid>>5)*2] = sum; red[(tid>>5)*2+1] = sq; }
    }
    __syncthreads();

    if (tid < 64) {
        float sum = red[0] + red[2], sq = red[1] + red[3];
        float m = sum * (1.f/64.f);
        float var = sq * (1.f/64.f) - m*m;
        float r = rsqrtf(var + LN_EPS);
        mln[tid] = (act[tid] - m)*r*ln_mlp_w[tid] + ln_mlp_b[tid];
    }
    __syncthreads();

    if (tid < 128) {
        float a0 = b1[tid], a1 = 0.f, a2 = 0.f, a3 = 0.f;
        #pragma unroll 8
        for (int e = 0; e < 64; e += 4) {
            a0 = fmaf(mln[e],   g_W1T[e*128 + tid],     a0);
            a1 = fmaf(mln[e+1], g_W1T[(e+1)*128 + tid], a1);
            a2 = fmaf(mln[e+2], g_W1T[(e+2)*128 + tid], a2);
            a3 = fmaf(mln[e+3], g_W1T[(e+3)*128 + tid], a3);
        }
        h1[tid] = fmaxf((a0 + a1) + (a2 + a3), 0.f);
    }
    __syncthreads();

    float res = 0.f;
    if (tid < 64) {
        float a0 = b2[tid], a1 = 0.f, a2 = 0.f, a3 = 0.f;
        #pragma unroll 8
        for (int j = 0; j < 128; j += 4) {
            a0 = fmaf(h1[j],   g_W2T[j*64 + tid],     a0);
            a1 = fmaf(h1[j+1], g_W2T[(j+1)*64 + tid], a1);
            a2 = fmaf(h1[j+2], g_W2T[(j+2)*64 + tid], a2);
            a3 = fmaf(h1[j+3], g_W2T[(j+3)*64 + tid], a3);
        }
        res = act[tid] + (a0 + a1) + (a2 + a3);
        g_slots[bs*64 + tid] = res;
        if (last) out[bs*64 + tid] = res;
    }
    if (last) return;
    __syncthreads();

    if (tid < 64) {
        float sum = res, sq = res*res;
        #pragma unroll
        for (int o = 16; o; o >>= 1) {
            sum += __shfl_xor_sync(0xffffffffu, sum, o);
            sq  += __shfl_xor_sync(0xffffffffu, sq,  o);
        }
        if ((tid & 31) == 0) { red[(tid>>5)*2] = sum; red[(tid>>5)*2+1] = sq; }
        g_u[bs*64 + tid] = 0.f;
    }
    if (tid == 0) { g_den[bs] = 0.f; g_c2[bs] = 0.f; }
    __syncthreads();

    if (tid < 64) {
        float sum = red[0] + red[2], sq = red[1] + red[3];
        float m = sum * (1.f/64.f);
        float var = sq * (1.f/64.f) - m*m;
        float r = rsqrtf(var + LN_EPS);
        mln[tid] = (res - m)*r*ln_slots_w[tid] + ln_slots_b[tid];
    }
    __syncthreads();

    if (tid < 64) {
        float a0 = 0.f, a1 = 0.f, a2 = 0.f, a3 = 0.f;
        #pragma unroll 8
        for (int e = 0; e < 64; e += 4) {
            a0 = fmaf(mln[e],   g_M[e*64 + tid],     a0);
            a1 = fmaf(mln[e+1], g_M[(e+1)*64 + tid], a1);
            a2 = fmaf(mln[e+2], g_M[(e+2)*64 + tid], a2);
            a3 = fmaf(mln[e+3], g_M[(e+3)*64 + tid], a3);
        }
        float acc = (a0 + a1) + (a2 + a3);
        g_qt[bs*64 + tid] = acc * ln_in_w[tid];
        float pa = acc * ln_in_w[tid];
        float pb = acc * ln_in_b[tid];
        #pragma unroll
        for (int o = 16; o; o >>= 1) {
            pa += __shfl_xor_sync(0xffffffffu, pa, o);
            pb += __shfl_xor_sync(0xffffffffu, pb, o);
        }
        if ((tid & 31) == 0) { red[(tid>>5)*2] = pa; red[(tid>>5)*2+1] = pb; }
    }
    __syncthreads();
    if (tid == 0) {
        g_qsc[bs*2 + 0] = red[0] + red[2];
        g_qsc[bs*2 + 1] = red[1] + red[3];
    }
}

// ---------------------------------------------------------------------------
extern "C" void kernel_launch(void* const* d_in, const int* in_sizes, int n_in,
                              void* d_out, int out_size) {
    const float* inputs     = (const float*)d_in[0];
    const float* noise      = (const float*)d_in[1];
    const float* ln_in_w    = (const float*)d_in[2];
    const float* ln_in_b    = (const float*)d_in[3];
    const float* ln_slots_w = (const float*)d_in[4];
    const float* ln_slots_b = (const float*)d_in[5];
    const float* ln_mlp_w   = (const float*)d_in[6];
    const float* ln_mlp_b   = (const float*)d_in[7];
    const float* mu         = (const float*)d_in[8];
    const float* logsig     = (const float*)d_in[9];
    const float* Wq         = (const float*)d_in[10];
    const float* Wk         = (const float*)d_in[11];
    const float* Wv         = (const float*)d_in[12];
    const float* W_ih       = (const float*)d_in[13];
    const float* W_hh       = (const float*)d_in[14];
    const float* b_ih       = (const float*)d_in[15];
    const float* b_hh       = (const float*)d_in[16];
    const float* W1         = (const float*)d_in[17];
    const float* b1         = (const float*)d_in[18];
    const float* W2         = (const float*)d_in[19];
    const float* b2         = (const float*)d_in[20];
    float* out = (float*)d_out;

    cudaFuncSetAttribute(k_attn<1>, cudaFuncAttributeMaxDynamicSharedMemorySize,
                         AT_BYTES);
    cudaFuncSetAttribute(k_attn<0>, cudaFuncAttributeMaxDynamicSharedMemorySize,
                         AT_BYTES);

    cudaLaunchAttribute pdlAttr[1];
    pdlAttr[0].id = cudaLaunchAttributeProgrammaticStreamSerialization;
    pdlAttr[0].val.programmaticStreamSerializationAllowed = 1;

    k_precomp<<<176, 256>>>(Wq, Wk, W_ih, Wv, W_hh, W1, W2);

    {
        cudaLaunchConfig_t cfg = {};
        cfg.gridDim = dim3(BB); cfg.blockDim = dim3(256);
        cfg.attrs = pdlAttr; cfg.numAttrs = 1;
        cudaLaunchKernelEx(&cfg, k_q0, noise, mu, logsig,
                           ln_slots_w, ln_slots_b, ln_in_w, ln_in_b);
    }

    dim3 grid(NN/TT, BB);
    for (int it = 0; it < NUM_ITERS; it++) {
        {
            cudaLaunchConfig_t cfg = {};
            cfg.gridDim = grid; cfg.blockDim = dim3(256);
            cfg.dynamicSmemBytes = AT_BYTES;
            cfg.attrs = pdlAttr; cfg.numAttrs = 1;
            if (it == 0) cudaLaunchKernelEx(&cfg, k_attn<1>, inputs);
            else         cudaLaunchKernelEx(&cfg, k_attn<0>, inputs);
        }
        {
            cudaLaunchConfig_t cfg = {};
            cfg.gridDim = dim3(BB*SS); cfg.blockDim = dim3(192);
            cfg.attrs = pdlAttr; cfg.numAttrs = 1;
            int last  = (it == NUM_ITERS - 1) ? 1 : 0;
            int early = (it == 0) ? 0 : 1;
            cudaLaunchKernelEx(&cfg, k_finalize, b_ih, b_hh, b1, b2,
                               ln_mlp_w, ln_mlp_b, ln_slots_w, ln_slots_b,
                               ln_in_w, ln_in_b, out, last, early);
        }
    }
}

// round 17
// speedup vs baseline: 1.1495x; 1.1495x over previous
#include <cuda_runtime.h>
#include <cuda_fp16.h>
#include <math.h>

#define BB 128
#define NN 4096
#define DD 64
#define SS 7
#define HH 128
#define NUM_ITERS 3
#define EPSV 1e-8f
#define LN_EPS 1e-5f
#define SCALE 0.125f   // 64^-0.5

typedef unsigned long long u64;
typedef unsigned int u32;

#define PDL_TRIGGER() asm volatile("griddepcontrol.launch_dependents;")
#define PDL_WAIT()    asm volatile("griddepcontrol.wait;" ::: "memory")

// persistent scratch (no allocation allowed)
__device__ float g_slots[BB*SS*DD];
__device__ float g_qt[BB*SS*DD];    // qw = ln_in_w ⊙ (q@Wk)  [b][s][64]
__device__ float g_qsc[BB*SS*2];    // {sw, sb} per (b,s)
__device__ float g_u[BB*SS*DD];     // G1 = sum_n (p*r) * x
__device__ float g_den[BB*SS];      // sum_n p
__device__ float g_c2[BB*SS];       // sum_n p*r*m
__device__ float g_M[DD*DD];        // scale * Wq^T @ Wk      [e][t]
__device__ float g_CT[DD*3*DD];     // (W_ih @ Wv)^T          [e][j]
__device__ float g_WHHT[DD*3*DD];   // W_hh^T                 [e][j]
__device__ float g_W1T[DD*HH];      // W1^T                   [e][j]
__device__ float g_W2T[HH*DD];      // W2^T                   [j][d]
__device__ __half g_xh[(size_t)BB*NN*DD];   // fp16 shadow of inputs (67MB)
__device__ float g_sq[(size_t)BB*NN];       // per-token sumsq cache (2MB)

// ---------------------------------------------------------------------------
__device__ __forceinline__ float fexp(float x){
    float t = fmaxf(x * 1.4426950408889634f, -126.f);
    float z = __fadd_rn(t, 12582912.f);
    int n = __float_as_int(z) - 0x4B400000;
    float f = t - __fsub_rn(z, 12582912.f);
    float p =         1.5403530e-4f;
    p = fmaf(p, f,    1.3333558e-3f);
    p = fmaf(p, f,    9.6181291e-3f);
    p = fmaf(p, f,    5.5504109e-2f);
    p = fmaf(p, f,    2.4022651e-1f);
    p = fmaf(p, f,    6.9314718e-1f);
    p = fmaf(p, f,    1.0f);
    return p * __int_as_float((n + 127) << 23);
}
__device__ __forceinline__ float ftanh(float x){
    return 1.f - __fdividef(2.f, 1.f + __expf(2.f*x));
}
__device__ __forceinline__ u32 smaddr(const void* p){
    return (u32)__cvta_generic_to_shared(p);
}
__device__ __forceinline__ void ldm_x4(u32& r0, u32& r1, u32& r2, u32& r3, u32 a){
    asm volatile("ldmatrix.sync.aligned.m8n8.x4.shared.b16 {%0,%1,%2,%3}, [%4];"
                 : "=r"(r0), "=r"(r1), "=r"(r2), "=r"(r3) : "r"(a));
}
__device__ __forceinline__ void ldm_x2t(u32& r0, u32& r1, u32 a){
    asm volatile("ldmatrix.sync.aligned.m8n8.x2.trans.shared.b16 {%0,%1}, [%2];"
                 : "=r"(r0), "=r"(r1) : "r"(a));
}
__device__ __forceinline__ void mma16816(float& d0, float& d1, float& d2, float& d3,
                                         u32 a0, u32 a1, u32 a2, u32 a3,
                                         u32 b0, u32 b1){
    asm volatile("mma.sync.aligned.m16n8k16.row.col.f32.f16.f16.f32 "
                 "{%0,%1,%2,%3}, {%4,%5,%6,%7}, {%8,%9}, {%0,%1,%2,%3};"
                 : "+f"(d0), "+f"(d1), "+f"(d2), "+f"(d3)
                 : "r"(a0), "r"(a1), "r"(a2), "r"(a3), "r"(b0), "r"(b1));
}

// ---------------------------------------------------------------------------
__global__ void k_precomp(const float* __restrict__ Wq,
                          const float* __restrict__ Wk,
                          const float* __restrict__ W_ih,
                          const float* __restrict__ Wv,
                          const float* __restrict__ W_hh,
                          const float* __restrict__ W1,
                          const float* __restrict__ W2) {
    int bi = blockIdx.x, t = threadIdx.x;
    if (bi < 16) {
        int o = bi*256 + t;
        int e = o >> 6, tc = o & 63;
        float acc = 0.f;
        #pragma unroll 8
        for (int d = 0; d < 64; d++)
            acc += Wq[d*64 + e] * Wk[d*64 + tc];
        g_M[e*64 + tc] = acc * SCALE;
    } else if (bi < 64) {
        int o = (bi-16)*256 + t;
        int e = o / 192, j = o - e*192;
        float acc = 0.f;
        #pragma unroll 8
        for (int h = 0; h < 64; h++)
            acc += W_ih[j*64 + h] * Wv[h*64 + e];
        g_CT[o] = acc;
    } else {
        int idx = (bi-64)*256 + t;
        if (idx < 12288) {
            int e = idx / 192, j = idx - e*192;
            g_WHHT[idx] = W_hh[j*64 + e];
        } else if (idx < 20480) {
            int o = idx - 12288;
            int e = o >> 7, j = o & 127;
            g_W1T[o] = W1[j*64 + e];
        } else {
            int o = idx - 20480;
            int j = o >> 6, d = o & 63;
            g_W2T[o] = W2[d*128 + j];
        }
    }
}

// ---------------------------------------------------------------------------
__global__ void k_q0(const float* __restrict__ noise,
                     const float* __restrict__ mu,
                     const float* __restrict__ logsig,
                     const float* __restrict__ lnw,
                     const float* __restrict__ lnb,
                     const float* __restrict__ w_in,
                     const float* __restrict__ b_in) {
    int b = blockIdx.x;
    int tid = threadIdx.x;
    int w = tid >> 5, lane = tid & 31;
    __shared__ float sl[SS*64];
    __shared__ float sn[SS*64];
    __shared__ float qtmp[SS*64];

    PDL_TRIGGER();

    for (int i = tid; i < SS*64; i += 256) {
        int d = i & 63;
        float v = mu[d] + expf(logsig[d]) * noise[b*SS*64 + i];
        g_slots[b*SS*64 + i] = v;
        sl[i] = v;
        g_u[b*SS*64 + i] = 0.f;
    }
    if (tid < SS) { g_den[b*SS + tid] = 0.f; g_c2[b*SS + tid] = 0.f; }
    __syncthreads();

    if (w < SS) {
        float v0 = sl[w*64 + lane], v1 = sl[w*64 + lane+32];
        float sum = v0 + v1, sq = v0*v0 + v1*v1;
        #pragma unroll
        for (int o = 16; o; o >>= 1) {
            sum += __shfl_xor_sync(0xffffffffu, sum, o);
            sq  += __shfl_xor_sync(0xffffffffu, sq,  o);
        }
        float mean = sum * (1.f/64.f);
        float var  = sq  * (1.f/64.f) - mean*mean;
        float rstd = rsqrtf(var + LN_EPS);
        sn[w*64 + lane]    = (v0 - mean)*rstd*lnw[lane]    + lnb[lane];
        sn[w*64 + lane+32] = (v1 - mean)*rstd*lnw[lane+32] + lnb[lane+32];
    }
    PDL_WAIT();
    __syncthreads();

    for (int i = tid; i < SS*64; i += 256) {
        int s = i >> 6, tc = i & 63;
        float acc = 0.f;
        #pragma unroll 8
        for (int e = 0; e < 64; e++)
            acc += sn[s*64 + e] * g_M[e*64 + tc];
        qtmp[i] = acc;
        g_qt[b*SS*64 + i] = acc * w_in[tc];
    }
    __syncthreads();
    if (tid < 14) {
        int s = tid >> 1;
        float acc = 0.f;
        if ((tid & 1) == 0) {
            for (int tc = 0; tc < 64; tc++) acc += qtmp[s*64+tc] * w_in[tc];
        } else {
            for (int tc = 0; tc < 64; tc++) acc += qtmp[s*64+tc] * b_in[tc];
        }
        g_qsc[b*SS*2 + tid] = acc;
    }
}

// ---------------------------------------------------------------------------
// Tensor-core streaming pass, 256-token tiles (2048 blocks).
// smem bytes:
//   XH  fp16 [256][72]  : 0      .. 36864
//   PRS fp16 [16][264]  : 36864  .. 45312   (rows 0..6 valid)
//   QH  fp16 [8][68]    : 45312  .. 46400   (row 7 = ones -> sum column)
//   SQV f32  [256]      : 46400  .. 47424
//   QSC f32  [14]       : 47424  .. 47480
#define O_XH   0
#define O_PRS  36864
#define O_QH   45312
#define O_SQV  46400
#define O_QSC  47424
#define AT_BYTES 47488
#define TT 256   // tokens per tile

template<int FIRST>
__global__ void __launch_bounds__(256) k_attn(const float* __restrict__ inputs) {
    extern __shared__ char sm[];
    __half* xh  = (__half*)(sm + O_XH);
    __half* prs = (__half*)(sm + O_PRS);
    __half* qh  = (__half*)(sm + O_QH);
    float*  sqv = (float*)(sm + O_SQV);
    float*  qsc = (float*)(sm + O_QSC);

    int b = blockIdx.y, tile = blockIdx.x;
    int tid = threadIdx.x;
    int w = tid >> 5, lane = tid & 31;
    int g = lane >> 2, q = lane & 3;

    PDL_TRIGGER();

    size_t base = ((size_t)b*NN + (size_t)tile*TT) * DD;
    size_t sqbase = (size_t)b*NN + (size_t)tile*TT;
    if (FIRST) {
        const float4* src4 = (const float4*)(inputs + base);
        __half2* dsth = (__half2*)(g_xh + base);
        #pragma unroll
        for (int k = 0; k < 16; k++) {
            int idx = tid + 256*k;
            float4 v = src4[idx];
            int token = idx >> 4, ch = idx & 15;
            __half2 h0 = __floats2half2_rn(v.x, v.y);
            __half2 h1 = __floats2half2_rn(v.z, v.w);
            uint2 pk2;
            pk2.x = *(u32*)&h0; pk2.y = *(u32*)&h1;
            *(uint2*)(xh + token*72 + ch*4) = pk2;
            *(uint2*)(dsth + idx*2) = pk2;
        }
        __syncthreads();
        // per-token sumsq (thread tid owns token tid); cache to g_sq
        {
            const uint4* p = (const uint4*)(xh + tid*72);
            float sq = 0.f;
            #pragma unroll
            for (int j = 0; j < 8; j++) {
                uint4 v = p[j];
                float2 f;
                f = __half22float2(*(__half2*)&v.x); sq = fmaf(f.x,f.x,fmaf(f.y,f.y,sq));
                f = __half22float2(*(__half2*)&v.y); sq = fmaf(f.x,f.x,fmaf(f.y,f.y,sq));
                f = __half22float2(*(__half2*)&v.z); sq = fmaf(f.x,f.x,fmaf(f.y,f.y,sq));
                f = __half22float2(*(__half2*)&v.w); sq = fmaf(f.x,f.x,fmaf(f.y,f.y,sq));
            }
            sqv[tid] = sq;
            g_sq[sqbase + tid] = sq;
        }
    } else {
        const uint4* srch = (const uint4*)(g_xh + base);
        #pragma unroll
        for (int it = 0; it < 8; it++) {
            int idx = tid + 256*it;
            uint4 v = srch[idx];
            int token = idx >> 3, c8 = idx & 7;
            *(uint4*)(xh + token*72 + c8*8) = v;
        }
        sqv[tid] = g_sq[sqbase + tid];
    }

    PDL_WAIT();      // g_qt/g_qsc from predecessor

    for (int i = tid; i < 8*64; i += 256) {
        int s = i >> 6, k = i & 63;
        qh[s*68 + k] = (s < SS) ? __float2half(g_qt[b*SS*64 + s*64 + k])
                                : __float2half(1.0f);    // ones row -> sum
    }
    if (tid < 14) qsc[tid] = g_qsc[b*14 + tid];
    __syncthreads();

    // ---- phase A: two 16-token MMA groups per warp + softmax ----
    float dvA0 = 0.f, cvA0 = 0.f, dvA1 = 0.f, cvA1 = 0.f;
    u32 xh_s = smaddr(xh);
    int s0 = q*2, s1 = q*2 + 1;
    bool v1 = (s1 < SS);
    #pragma unroll
    for (int tg = 0; tg < 2; tg++) {
        int t0 = w*32 + tg*16;
        float d0 = 0.f, d1 = 0.f, d2 = 0.f, d3 = 0.f;
        #pragma unroll
        for (int kt = 0; kt < 4; kt++) {
            u32 a0, a1, a2, a3;
            u32 addr = xh_s + ((t0 + (lane & 15))*72 + kt*16 + (lane >> 4)*8)*2;
            ldm_x4(a0, a1, a2, a3, addr);
            u32 b01 = *(const u32*)(qh + g*68 + kt*16 + q*2);
            u32 b23 = *(const u32*)(qh + g*68 + kt*16 + 8 + q*2);
            mma16816(d0, d1, d2, d3, a0, a1, a2, a3, b01, b23);
        }
        int r0 = t0 + g, r1 = t0 + g + 8;
        float sum0 = __shfl_sync(0xffffffffu, d1, g*4 + 3);
        float sum1 = __shfl_sync(0xffffffffu, d3, g*4 + 3);
        float m0 = sum0 * (1.f/64.f), m1 = sum1 * (1.f/64.f);
        float rs0 = rsqrtf(fmaf(sqv[r0], 1.f/64.f, -m0*m0) + LN_EPS);
        float rs1 = rsqrtf(fmaf(sqv[r1], 1.f/64.f, -m1*m1) + LN_EPS);

        float lg00 = fmaf(rs0, d0 - m0*qsc[2*s0], qsc[2*s0+1]);
        float lg10 = fmaf(rs1, d2 - m1*qsc[2*s0], qsc[2*s0+1]);
        float lg01 = v1 ? fmaf(rs0, d1 - m0*qsc[2*s1], qsc[2*s1+1]) : -1e30f;
        float lg11 = v1 ? fmaf(rs1, d3 - m1*qsc[2*s1], qsc[2*s1+1]) : -1e30f;

        float mx0 = fmaxf(lg00, lg01), mx1 = fmaxf(lg10, lg11);
        #pragma unroll
        for (int o = 1; o <= 2; o <<= 1) {
            mx0 = fmaxf(mx0, __shfl_xor_sync(0xffffffffu, mx0, o));
            mx1 = fmaxf(mx1, __shfl_xor_sync(0xffffffffu, mx1, o));
        }
        float e00 = fexp(lg00 - mx0), e01 = v1 ? fexp(lg01 - mx0) : 0.f;
        float e10 = fexp(lg10 - mx1), e11 = v1 ? fexp(lg11 - mx1) : 0.f;
        float tot0 = e00 + e01, tot1 = e10 + e11;
        #pragma unroll
        for (int o = 1; o <= 2; o <<= 1) {
            tot0 += __shfl_xor_sync(0xffffffffu, tot0, o);
            tot1 += __shfl_xor_sync(0xffffffffu, tot1, o);
        }
        float inv0 = __fdividef(1.f, tot0), inv1 = __fdividef(1.f, tot1);

        float p00 = fmaf(e00, inv0, EPSV), p10 = fmaf(e10, inv1, EPSV);
        float p01 = fmaf(e01, inv0, EPSV), p11 = fmaf(e11, inv1, EPSV);
        float pr00 = p00*rs0, pr10 = p10*rs1;
        float pr01 = p01*rs0, pr11 = p11*rs1;

        prs[s0*264 + r0] = __float2half(pr00);
        prs[s0*264 + r1] = __float2half(pr10);
        if (v1) {
            prs[s1*264 + r0] = __float2half(pr01);
            prs[s1*264 + r1] = __float2half(pr11);
        }
        dvA0 += p00 + p10;  cvA0 += pr00*m0 + pr10*m1;
        if (v1) { dvA1 += p01 + p11;  cvA1 += pr01*m0 + pr11*m1; }
    }
    #pragma unroll
    for (int o = 4; o <= 16; o <<= 1) {
        dvA0 += __shfl_xor_sync(0xffffffffu, dvA0, o);
        cvA0 += __shfl_xor_sync(0xffffffffu, cvA0, o);
        dvA1 += __shfl_xor_sync(0xffffffffu, dvA1, o);
        cvA1 += __shfl_xor_sync(0xffffffffu, cvA1, o);
    }
    if (lane < 4) {
        int ss0 = lane*2, ss1 = lane*2 + 1;
        atomicAdd(&g_den[b*SS + ss0], dvA0);
        atomicAdd(&g_c2[b*SS + ss0],  cvA0);
        if (ss1 < SS) {
            atomicAdd(&g_den[b*SS + ss1], dvA1);
            atomicAdd(&g_c2[b*SS + ss1],  cvA1);
        }
    }
    __syncthreads();

    // ---- phase B: U = PR^T @ X via HMMA. warp w -> e-cols n0..n0+7 ----
    {
        int n0 = w*8;
        float u0 = 0.f, u1 = 0.f, u2 = 0.f, u3 = 0.f;
        u32 prs_s = smaddr(prs);
        #pragma unroll
        for (int kt = 0; kt < 16; kt++) {
            u32 a0, a1, a2, a3, b0, b1;
            u32 addrA = prs_s + ((lane & 15)*264 + kt*16 + (lane >> 4)*8)*2;
            ldm_x4(a0, a1, a2, a3, addrA);
            u32 addrB = xh_s + ((kt*16 + (lane & 15))*72 + n0)*2;
            ldm_x2t(b0, b1, addrB);
            mma16816(u0, u1, u2, u3, a0, a1, a2, a3, b0, b1);
        }
        if (g < SS) {
            float* up = g_u + (b*SS + g)*DD + n0 + q*2;
            atomicAdd(up + 0, u0);
            atomicAdd(up + 1, u1);
        }
        (void)u2; (void)u3;
    }
}

// ---------------------------------------------------------------------------
// finalize: one block per (batch, slot) = 896 blocks, 192 threads.
__global__ void __launch_bounds__(192, 4) k_finalize(
        const float* __restrict__ b_ih, const float* __restrict__ b_hh,
        const float* __restrict__ b1,  const float* __restrict__ b2,
        const float* __restrict__ ln_mlp_w, const float* __restrict__ ln_mlp_b,
        const float* __restrict__ ln_slots_w, const float* __restrict__ ln_slots_b,
        const float* __restrict__ ln_in_w, const float* __restrict__ ln_in_b,
        float* __restrict__ out, int last, int early) {
    __shared__ float upd[64], prev[64], giv[192], ghv[192],
                     act[64], mln[64], h1[128], red[8];
    int bs = blockIdx.x;
    int tid = threadIdx.x;

    if (early) PDL_TRIGGER();

    {   // prefetch weights while predecessor attn drains
        float acc = 0.f;
        #pragma unroll 8
        for (int e = 0; e < 64; e++)
            acc += g_CT[e*192 + tid] + g_WHHT[e*192 + tid];
        if (tid < 128) {
            #pragma unroll 8
            for (int e = 0; e < 64; e++) acc += g_W1T[e*128 + tid];
        }
        if (tid < 64) {
            #pragma unroll 8
            for (int j = 0; j < 128; j++) acc += g_W2T[j*64 + tid];
            #pragma unroll 8
            for (int e = 0; e < 64; e++) acc += g_M[e*64 + tid];
        }
        asm volatile("" :: "f"(acc));
    }

    PDL_WAIT();

    if (tid < 64) {
        float invden = __fdividef(1.f, g_den[bs]);
        upd[tid] = fmaf(ln_in_w[tid]*invden, g_u[bs*64 + tid] - g_c2[bs],
                        ln_in_b[tid]);
        prev[tid] = g_slots[bs*64 + tid];
    }
    __syncthreads();

    {
        float ai0 = b_ih[tid], ah0 = b_hh[tid];
        float ai1 = 0.f, ah1 = 0.f, ai2 = 0.f, ah2 = 0.f, ai3 = 0.f, ah3 = 0.f;
        #pragma unroll 8
        for (int e = 0; e < 64; e += 4) {
            ai0 = fmaf(upd[e],    g_CT[e*192 + tid],       ai0);
            ai1 = fmaf(upd[e+1],  g_CT[(e+1)*192 + tid],   ai1);
            ai2 = fmaf(upd[e+2],  g_CT[(e+2)*192 + tid],   ai2);
            ai3 = fmaf(upd[e+3],  g_CT[(e+3)*192 + tid],   ai3);
            ah0 = fmaf(prev[e],   g_WHHT[e*192 + tid],     ah0);
            ah1 = fmaf(prev[e+1], g_WHHT[(e+1)*192 + tid], ah1);
            ah2 = fmaf(prev[e+2], g_WHHT[(e+2)*192 + tid], ah2);
            ah3 = fmaf(prev[e+3], g_WHHT[(e+3)*192 + tid], ah3);
        }
        giv[tid] = (ai0 + ai1) + (ai2 + ai3);
        ghv[tid] = (ah0 + ah1) + (ah2 + ah3);
    }
    __syncthreads();

    if (tid < 64) {
        float r = 1.f/(1.f + __expf(-(giv[tid]     + ghv[tid])));
        float z = 1.f/(1.f + __expf(-(giv[64+tid]  + ghv[64+tid])));
        float n = ftanh(fmaf(r, ghv[128+tid], giv[128+tid]));
        float v = (1.f - z)*n + z*prev[tid];
        act[tid] = v;
        float sum = v, sq = v*v;
        #pragma unroll
        for (int o = 16; o; o >>= 1) {
            sum += __shfl_xor_sync(0xffffffffu, sum, o);
            sq  += __shfl_xor_sync(0xffffffffu, sq,  o);
        }
        if ((tid & 31) == 0) { red[(tid>>5)*2] = sum; red[(tid>>5)*2+1] = sq; }
    }
    __syncthreads();

    if (tid < 64) {
        float sum = red[0] + red[2], sq = red[1] + red[3];
        float m = sum * (1.f/64.f);
        float var = sq * (1.f/64.f) - m*m;
        float r = rsqrtf(var + LN_EPS);
        mln[tid] = (act[tid] - m)*r*ln_mlp_w[tid] + ln_mlp_b[tid];
    }
    __syncthreads();

    if (tid < 128) {
        float a0 = b1[tid], a1 = 0.f, a2 = 0.f, a3 = 0.f;
        #pragma unroll 8
        for (int e = 0; e < 64; e += 4) {
            a0 = fmaf(mln[e],   g_W1T[e*128 + tid],     a0);
            a1 = fmaf(mln[e+1], g_W1T[(e+1)*128 + tid], a1);
            a2 = fmaf(mln[e+2], g_W1T[(e+2)*128 + tid], a2);
            a3 = fmaf(mln[e+3], g_W1T[(e+3)*128 + tid], a3);
        }
        h1[tid] = fmaxf((a0 + a1) + (a2 + a3), 0.f);
    }
    __syncthreads();

    float res = 0.f;
    if (tid < 64) {
        float a0 = b2[tid], a1 = 0.f, a2 = 0.f, a3 = 0.f;
        #pragma unroll 8
        for (int j = 0; j < 128; j += 4) {
            a0 = fmaf(h1[j],   g_W2T[j*64 + tid],     a0);
            a1 = fmaf(h1[j+1], g_W2T[(j+1)*64 + tid], a1);
            a2 = fmaf(h1[j+2], g_W2T[(j+2)*64 + tid], a2);
            a3 = fmaf(h1[j+3], g_W2T[(j+3)*64 + tid], a3);
        }
        res = act[tid] + (a0 + a1) + (a2 + a3);
        g_slots[bs*64 + tid] = res;
        if (last) out[bs*64 + tid] = res;
    }
    if (last) return;
    __syncthreads();

    if (tid < 64) {
        float sum = res, sq = res*res;
        #pragma unroll
        for (int o = 16; o; o >>= 1) {
            sum += __shfl_xor_sync(0xffffffffu, sum, o);
            sq  += __shfl_xor_sync(0xffffffffu, sq,  o);
        }
        if ((tid & 31) == 0) { red[(tid>>5)*2] = sum; red[(tid>>5)*2+1] = sq; }
        g_u[bs*64 + tid] = 0.f;
    }
    if (tid == 0) { g_den[bs] = 0.f; g_c2[bs] = 0.f; }
    __syncthreads();

    if (tid < 64) {
        float sum = red[0] + red[2], sq = red[1] + red[3];
        float m = sum * (1.f/64.f);
        float var = sq * (1.f/64.f) - m*m;
        float r = rsqrtf(var + LN_EPS);
        mln[tid] = (res - m)*r*ln_slots_w[tid] + ln_slots_b[tid];
    }
    __syncthreads();

    if (tid < 64) {
        float a0 = 0.f, a1 = 0.f, a2 = 0.f, a3 = 0.f;
        #pragma unroll 8
        for (int e = 0; e < 64; e += 4) {
            a0 = fmaf(mln[e],   g_M[e*64 + tid],     a0);
            a1 = fmaf(mln[e+1], g_M[(e+1)*64 + tid], a1);
            a2 = fmaf(mln[e+2], g_M[(e+2)*64 + tid], a2);
            a3 = fmaf(mln[e+3], g_M[(e+3)*64 + tid], a3);
        }
        float acc = (a0 + a1) + (a2 + a3);
        g_qt[bs*64 + tid] = acc * ln_in_w[tid];
        float pa = acc * ln_in_w[tid];
        float pb = acc * ln_in_b[tid];
        #pragma unroll
        for (int o = 16; o; o >>= 1) {
            pa += __shfl_xor_sync(0xffffffffu, pa, o);
            pb += __shfl_xor_sync(0xffffffffu, pb, o);
        }
        if ((tid & 31) == 0) { red[(tid>>5)*2] = pa; red[(tid>>5)*2+1] = pb; }
    }
    __syncthreads();
    if (tid == 0) {
        g_qsc[bs*2 + 0] = red[0] + red[2];
        g_qsc[bs*2 + 1] = red[1] + red[3];
    }
}

// ---------------------------------------------------------------------------
extern "C" void kernel_launch(void* const* d_in, const int* in_sizes, int n_in,
                              void* d_out, int out_size) {
    const float* inputs     = (const float*)d_in[0];
    const float* noise      = (const float*)d_in[1];
    const float* ln_in_w    = (const float*)d_in[2];
    const float* ln_in_b    = (const float*)d_in[3];
    const float* ln_slots_w = (const float*)d_in[4];
    const float* ln_slots_b = (const float*)d_in[5];
    const float* ln_mlp_w   = (const float*)d_in[6];
    const float* ln_mlp_b   = (const float*)d_in[7];
    const float* mu         = (const float*)d_in[8];
    const float* logsig     = (const float*)d_in[9];
    const float* Wq         = (const float*)d_in[10];
    const float* Wk         = (const float*)d_in[11];
    const float* Wv         = (const float*)d_in[12];
    const float* W_ih       = (const float*)d_in[13];
    const float* W_hh       = (const float*)d_in[14];
    const float* b_ih       = (const float*)d_in[15];
    const float* b_hh       = (const float*)d_in[16];
    const float* W1         = (const float*)d_in[17];
    const float* b1         = (const float*)d_in[18];
    const float* W2         = (const float*)d_in[19];
    const float* b2         = (const float*)d_in[20];
    float* out = (float*)d_out;

    cudaFuncSetAttribute(k_attn<1>, cudaFuncAttributeMaxDynamicSharedMemorySize,
                         AT_BYTES);
    cudaFuncSetAttribute(k_attn<0>, cudaFuncAttributeMaxDynamicSharedMemorySize,
                         AT_BYTES);

    cudaLaunchAttribute pdlAttr[1];
    pdlAttr[0].id = cudaLaunchAttributeProgrammaticStreamSerialization;
    pdlAttr[0].val.programmaticStreamSerializationAllowed = 1;

    k_precomp<<<176, 256>>>(Wq, Wk, W_ih, Wv, W_hh, W1, W2);

    {
        cudaLaunchConfig_t cfg = {};
        cfg.gridDim = dim3(BB); cfg.blockDim = dim3(256);
        cfg.attrs = pdlAttr; cfg.numAttrs = 1;
        cudaLaunchKernelEx(&cfg, k_q0, noise, mu, logsig,
                           ln_slots_w, ln_slots_b, ln_in_w, ln_in_b);
    }

    dim3 grid(NN/TT, BB);
    for (int it = 0; it < NUM_ITERS; it++) {
        {
            cudaLaunchConfig_t cfg = {};
            cfg.gridDim = grid; cfg.blockDim = dim3(256);
            cfg.dynamicSmemBytes = AT_BYTES;
            cfg.attrs = pdlAttr; cfg.numAttrs = 1;
            if (it == 0) cudaLaunchKernelEx(&cfg, k_attn<1>, inputs);
            else         cudaLaunchKernelEx(&cfg, k_attn<0>, inputs);
        }
        {
            cudaLaunchConfig_t cfg = {};
            cfg.gridDim = dim3(BB*SS); cfg.blockDim = dim3(192);
            cfg.attrs = pdlAttr; cfg.numAttrs = 1;
            int last  = (it == NUM_ITERS - 1) ? 1 : 0;
            int early = (it == 0) ? 0 : 1;
            cudaLaunchKernelEx(&cfg, k_finalize, b_ih, b_hh, b1, b2,
                               ln_mlp_w, ln_mlp_b, ln_slots_w, ln_slots_b,
                               ln_in_w, ln_in_b, out, last, early);
        }
    }
}